// round 13
// baseline (speedup 1.0000x reference)
#include <cuda_runtime.h>

typedef unsigned long long u64t;

#define BB 8
#define TT 100
#define UU 64
#define ZZ 256   // 4U
#define PP 1000
#define NK 50
#define NKP 56   // padded row: [0..24]=k0..24, [25..27]=0, [28..52]=k25..49, [53..55]=0
#define BT (BB*TT) // 800
#define TC 20    // t-chunk size
#define NC 5     // number of chunks
#define KQ 4     // GEMM K-split factor (R9-proven)

// Scratch (__device__ globals — no allocation)
__device__ __align__(16) float d_xkq[KQ*BT*ZZ];  // xt @ kernel, K-quarters (no bias)
__device__ __align__(16) float d_g[BB*TT*NKP];   // ht @ W1[0:64], padded
__device__ __align__(16) float d_XW[1024*NKP];   // X @ W1[64:192] + b1, padded
__device__ __align__(16) float d_A[NC*BB*8*256*28];  // chunk totals

// per-(b,pchunk) sync counters, self-resetting
__device__ int q_arrive[64];
__device__ int q_done[64];

// ---- packed f32x2 helpers ---------------------------------------------------
__device__ __forceinline__ u64t f2pk(float lo, float hi) {
    u64t r; asm("mov.b64 %0,{%1,%2};" : "=l"(r) : "f"(lo), "f"(hi)); return r;
}
__device__ __forceinline__ u64t ffma2(u64t a, u64t b, u64t c) {
    u64t d; asm("fma.rn.f32x2 %0,%1,%2,%3;" : "=l"(d) : "l"(a), "l"(b), "l"(c)); return d;
}
__device__ __forceinline__ u64t fadd2(u64t a, u64t b) {
    u64t d; asm("add.rn.f32x2 %0,%1,%2;" : "=l"(d) : "l"(a), "l"(b)); return d;
}
__device__ __forceinline__ float2 f2up(u64t v) {
    float2 r; asm("mov.b64 {%0,%1},%2;" : "=f"(r.x), "=f"(r.y) : "l"(v)); return r;
}
__device__ __forceinline__ float tanha(float x) {
    float y; asm("tanh.approx.f32 %0, %1;" : "=f"(y) : "f"(x)); return y;
}
__device__ __forceinline__ float siga(float x) {
    return fmaf(0.5f, tanha(0.5f * x), 0.5f);
}
__device__ __forceinline__ int padpos(int k) { return (k < 25) ? k : k + 3; }

__device__ __forceinline__ int ld_acq(int* p) {
    int v; asm volatile("ld.acquire.gpu.global.s32 %0, [%1];" : "=r"(v) : "l"(p) : "memory");
    return v;
}

// ---------------------------------------------------------------------------
// k_pre: blocks 0..415   -> xk GEMM, K split in 4 quarters (64x32 tiles, K=64)
//        blocks 416..540 -> XW[p,:] = X[p,:] @ W1b + b1  (8 p per block)
// (exact R9 structure)
// ---------------------------------------------------------------------------
__global__ void __launch_bounds__(256) k_pre(
    const int* __restrict__ pro_id, const int* __restrict__ label,
    const float* __restrict__ X, const float* __restrict__ onehot,
    const float* __restrict__ Kmat,
    const float* __restrict__ W1, const float* __restrict__ b1) {
    __shared__ union {
        struct { float A[32][64]; float B[32][32]; } g;
        struct { float W[128*52]; float Xr[8][128]; } w;
    } sh;
    int tid = threadIdx.x;
    int bx = blockIdx.x;

    if (bx < 104*KQ) {
        int kquart = bx / 104;
        int sub    = bx % 104;
        int mblk = sub % 13, nblk = sub / 13;
        int rowBase = mblk * 64;
        int n0 = nblk * 32;
        int kbase = kquart * 64;
        float* xkout = d_xkq + kquart*BT*ZZ;
        int ty = tid >> 4, tx = tid & 15;

        int m0 = tid >> 3;
        int kq = (tid & 7) * 4;
        int row0 = rowBase + m0, row1 = rowBase + m0 + 32;
        bool v0 = row0 < BT, v1 = row1 < BT;
        const float *xp0 = 0, *op0 = 0, *xp1 = 0, *op1 = 0;
        if (v0) { xp0 = X + pro_id[row0]*128; op0 = onehot + label[row0]*ZZ; }
        if (v1) { xp1 = X + pro_id[row1]*128; op1 = onehot + label[row1]*ZZ; }

        u64t acc2[2][2] = {{0ull,0ull},{0ull,0ull}};

        for (int k0 = kbase; k0 < kbase + 64; k0 += 32) {
            int i0 = k0 + kq;
            {
                float4 v = make_float4(0.f,0.f,0.f,0.f);
                if (v0) {
                    float4 xv = *(const float4*)&xp0[i0 & 127];
                    float4 ov = *(const float4*)&op0[i0];
                    v = make_float4(xv.x*ov.x, xv.y*ov.y, xv.z*ov.z, xv.w*ov.w);
                }
                sh.g.A[kq+0][m0] = v.x; sh.g.A[kq+1][m0] = v.y;
                sh.g.A[kq+2][m0] = v.z; sh.g.A[kq+3][m0] = v.w;
            }
            {
                float4 v = make_float4(0.f,0.f,0.f,0.f);
                if (v1) {
                    float4 xv = *(const float4*)&xp1[i0 & 127];
                    float4 ov = *(const float4*)&op1[i0];
                    v = make_float4(xv.x*ov.x, xv.y*ov.y, xv.z*ov.z, xv.w*ov.w);
                }
                sh.g.A[kq+0][m0+32] = v.x; sh.g.A[kq+1][m0+32] = v.y;
                sh.g.A[kq+2][m0+32] = v.z; sh.g.A[kq+3][m0+32] = v.w;
            }
            {
                int kk = tid >> 3;
                int n4 = (tid & 7) * 4;
                *(float4*)&sh.g.B[kk][n4] = *(const float4*)&Kmat[(k0 + kk)*256 + n0 + n4];
            }
            __syncthreads();
#pragma unroll
            for (int kk = 0; kk < 32; ++kk) {
                longlong2 av = *(const longlong2*)&sh.g.A[kk][ty*4];
                float2 bv = *(const float2*)&sh.g.B[kk][tx*2];
                u64t bx0 = f2pk(bv.x, bv.x);
                u64t bx1 = f2pk(bv.y, bv.y);
                acc2[0][0] = ffma2((u64t)av.x, bx0, acc2[0][0]);
                acc2[1][0] = ffma2((u64t)av.y, bx0, acc2[1][0]);
                acc2[0][1] = ffma2((u64t)av.x, bx1, acc2[0][1]);
                acc2[1][1] = ffma2((u64t)av.y, bx1, acc2[1][1]);
            }
            __syncthreads();
        }
#pragma unroll
        for (int mp = 0; mp < 2; ++mp) {
            float2 c0 = f2up(acc2[mp][0]);
            float2 c1 = f2up(acc2[mp][1]);
            int r0 = rowBase + ty*4 + 2*mp;
            if (r0 < BT) {
                xkout[r0*ZZ + n0 + tx*2]     = c0.x;
                xkout[r0*ZZ + n0 + tx*2 + 1] = c1.x;
            }
            if (r0 + 1 < BT) {
                xkout[(r0+1)*ZZ + n0 + tx*2]     = c0.y;
                xkout[(r0+1)*ZZ + n0 + tx*2 + 1] = c1.y;
            }
        }
    } else {
        // ---- XW part ----
        int pbase = (bx - 104*KQ) * 8;
        for (int idx = tid; idx < 128*NK; idx += 256) {
            int j = idx / NK, k = idx - j*NK;
            sh.w.W[j*52 + k] = __ldg(&W1[(64 + j)*NK + k]);
        }
        {
            int pl = tid >> 5, quad = tid & 31;
            ((float4*)sh.w.Xr[pl])[quad] = *(const float4*)&X[(pbase + pl)*128 + quad*4];
        }
        __syncthreads();

        int pl = tid >> 5, lane = tid & 31;
        int p = pbase + pl;
        if (lane < 25) {
            int k2 = lane * 2;
            u64t acc = f2pk(__ldg(&b1[k2]), __ldg(&b1[k2+1]));
            const float* xr = sh.w.Xr[pl];
#pragma unroll 8
            for (int j = 0; j < 128; ++j) {
                float x = xr[j];
                acc = ffma2(f2pk(x, x), *(const u64t*)&sh.w.W[j*52 + k2], acc);
            }
            float2 r = f2up(acc);
            d_XW[p*NKP + padpos(k2)]     = r.x;
            d_XW[p*NKP + padpos(k2 + 1)] = r.y;
        } else if (lane < 31) {
            int off = (lane <= 27) ? lane : lane + 25;
            d_XW[p*NKP + off] = 0.f;
        }
    }
}

// ---------------------------------------------------------------------------
// k_lstm: shuffle-gate layout. Thread tid: gate = tid&3, unit j = tid>>2.
// All 4 gate pre-activations of unit j live in adjacent lanes of one warp:
// activations gathered with 4 shuffles; c/h updated redundantly in 4 lanes;
// gate-0 lane stores h; ONE __syncthreads per step (h_hist slot per t).
// ---------------------------------------------------------------------------
__global__ void __launch_bounds__(256) k_lstm(const float* __restrict__ rec,
                                              const float* __restrict__ bias,
                                              const float* __restrict__ W1) {
    int b = blockIdx.x;
    int tid = threadIdx.x;
    int gate = tid & 3;
    int j    = tid >> 2;                 // unit 0..63
    int col  = (gate << 6) | j;          // z column: keras [i,f,g,o] chunks
    __shared__ __align__(16) float h_hist[TT][UU];

    u64t rc2[32];
#pragma unroll
    for (int m = 0; m < 32; ++m)
        rc2[m] = f2pk(rec[(2*m)*ZZ + col], rec[(2*m+1)*ZZ + col]);

    float bs = __ldg(&bias[col]);
    float c = 0.f;
    int lb = (tid & 31) & ~3;            // lane base of this unit's quartet

    const float* xq = d_xkq + b*TT*ZZ + col;
    float xs;
    {
        float s = bs;
#pragma unroll
        for (int q = 0; q < KQ; ++q) s += xq[q*BT*ZZ];
        xs = s;
    }

#pragma unroll 1
    for (int t = 0; t < TT; ++t) {
        float xk = xs;
        float nv[KQ];
#pragma unroll
        for (int q = 0; q < KQ; ++q) nv[q] = 0.f;
        if (t + 1 < TT) {
            int o = (t + 1) * ZZ;
#pragma unroll
            for (int q = 0; q < KQ; ++q) nv[q] = xq[o + q*BT*ZZ];
        }
        float z;
        if (t == 0) {
            z = xk;
        } else {
            const longlong2* h8 = (const longlong2*)h_hist[t-1];
            u64t z0 = f2pk(xk, 0.f), z1 = 0ull, z2 = 0ull, z3 = 0ull;
#pragma unroll
            for (int i = 0; i < 8; ++i) {
                longlong2 hA = h8[i], hB = h8[i+8];
                z0 = ffma2((u64t)hA.x, rc2[2*i],    z0);
                z1 = ffma2((u64t)hA.y, rc2[2*i+1],  z1);
                z2 = ffma2((u64t)hB.x, rc2[2*i+16], z2);
                z3 = ffma2((u64t)hB.y, rc2[2*i+17], z3);
            }
            float2 r = f2up(fadd2(fadd2(z0, z1), fadd2(z2, z3)));
            z = r.x + r.y;
        }
        float a = (gate == 2) ? tanha(z) : siga(z);
        float ai = __shfl_sync(0xffffffffu, a, lb + 0);
        float af = __shfl_sync(0xffffffffu, a, lb + 1);
        float ag = __shfl_sync(0xffffffffu, a, lb + 2);
        float ao = __shfl_sync(0xffffffffu, a, lb + 3);
        c = fmaf(af, c, ai*ag);
        float h = ao * tanha(c);
        if (gate == 0) h_hist[t][j] = h;
        __syncthreads();
        {
            float s = bs;
#pragma unroll
            for (int q = 0; q < KQ; ++q) s += nv[q];
            xs = s;
        }
    }

    // epilogue: g[b,t,k] = sum_u h[t][u] * W1[u*50+k]
    int k = tid & 63, tc = tid >> 6;
    if (k < NK) {
        u64t w1c[32];
#pragma unroll
        for (int m = 0; m < 32; ++m)
            w1c[m] = f2pk(__ldg(&W1[(2*m)*NK + k]), __ldg(&W1[(2*m+1)*NK + k]));
        int off = padpos(k);
#pragma unroll 1
        for (int tt = tc*25; tt < tc*25 + 25; ++tt) {
            const longlong2* h8 = (const longlong2*)h_hist[tt];
            u64t g0 = 0ull, g1 = 0ull, g2 = 0ull, g3 = 0ull;
#pragma unroll
            for (int i = 0; i < 8; ++i) {
                longlong2 hA = h8[i], hB = h8[i+8];
                g0 = ffma2((u64t)hA.x, w1c[2*i],    g0);
                g1 = ffma2((u64t)hA.y, w1c[2*i+1],  g1);
                g2 = ffma2((u64t)hB.x, w1c[2*i+16], g2);
                g3 = ffma2((u64t)hB.y, w1c[2*i+17], g3);
            }
            float2 r = f2up(fadd2(fadd2(g0, g1), fadd2(g2, g3)));
            d_g[(b*TT + tt)*NKP + off] = r.x + r.y;
        }
    } else if (k < 56) {
        int off = (k >= 53) ? k : (k - 25);
        for (int tt = tc*25; tt < tc*25 + 25; ++tt)
            d_g[(b*TT + tt)*NKP + off] = 0.f;
    }
}

// ---------------------------------------------------------------------------
// k_main: fused two-level suffix scan (R9-exact), spin-sync within co-resident
// 320 blocks. Grid (pchunk=8, b=8, c=5).
// ---------------------------------------------------------------------------
__global__ void __launch_bounds__(256) k_main(
    const int* __restrict__ pro_id, const float* __restrict__ cosX,
    const float* __restrict__ W2, const float* __restrict__ b2,
    float* __restrict__ out) {
    __shared__ __align__(16) float g_sh[TC*NKP];
    __shared__ int pid_sh[TC];

    int pc8 = blockIdx.x;
    int b   = blockIdx.y;
    int c   = blockIdx.z;
    int tid = threadIdx.x;
    int t0  = c * TC;
    int qidx = b*8 + pc8;

    {
        const float4* gg = (const float4*)&d_g[(b*TT + t0)*NKP];
        float4* gs = (float4*)g_sh;
        for (int i = tid; i < (TC*NKP)/4; i += 256) gs[i] = gg[i];
        if (tid < TC) pid_sh[tid] = pro_id[b*TT + t0 + tid];
    }
    __syncthreads();

    int p    = pc8*128 + (tid >> 1);
    int half = tid & 1;
    bool valid = (p < PP);
    int pc = valid ? p : (PP - 1);

    long aoff = ((long)((c*BB + b)*8 + pc8)*256 + tid) * 28;

    // ---- Phase A: own-chunk total (c>0 only), packed ----
    if (c > 0) {
        u64t accA[14];
#pragma unroll
        for (int m = 0; m < 14; ++m) accA[m] = 0ull;
#pragma unroll 1
        for (int tt = 0; tt < TC; ++tt) {
            float av = __ldg(&cosX[pid_sh[tt]*PP + pc]);
            u64t av2 = f2pk(av, av);
            const longlong2* g2 = (const longlong2*)&g_sh[tt*NKP + half*28];
#pragma unroll
            for (int m = 0; m < 7; ++m) {
                longlong2 gv = g2[m];
                accA[2*m]   = ffma2(av2, (u64t)gv.x, accA[2*m]);
                accA[2*m+1] = ffma2(av2, (u64t)gv.y, accA[2*m+1]);
            }
        }
        longlong2* dst = (longlong2*)&d_A[aoff];
#pragma unroll
        for (int m = 0; m < 7; ++m)
            dst[m] = make_longlong2((long long)accA[2*m], (long long)accA[2*m+1]);
        __threadfence();
    }
    __syncthreads();
    if (tid == 0)
        asm volatile("red.release.gpu.global.add.s32 [%0], 1;" :: "l"(&q_arrive[qidx]) : "memory");

    // ---- preload while waiting ----
    u64t acc[14];
    float w2r[28];
    {
        const longlong2* x2 = (const longlong2*)&d_XW[p*NKP + half*28];
#pragma unroll
        for (int m = 0; m < 7; ++m) {
            longlong2 v = x2[m];
            acc[2*m] = (u64t)v.x; acc[2*m+1] = (u64t)v.y;
        }
    }
#pragma unroll
    for (int jj = 0; jj < 28; ++jj)
        w2r[jj] = (jj < 25) ? __ldg(&W2[half*25 + jj]) : 0.f;
    float b2v = __ldg(b2);

    // ---- wait for all chunks of this (b,pchunk) ----
    if (tid == 0) {
        while (ld_acq(&q_arrive[qidx]) < NC) __nanosleep(60);
    }
    __syncthreads();

    // ---- tail: sum A of chunks > c ----
    for (int c2 = c + 1; c2 < NC; ++c2) {
        long o2 = ((long)((c2*BB + b)*8 + pc8)*256 + tid) * 28;
        const longlong2* src = (const longlong2*)&d_A[o2];
#pragma unroll
        for (int m = 0; m < 7; ++m) {
            longlong2 v = src[m];
            acc[2*m]   = fadd2(acc[2*m],   (u64t)v.x);
            acc[2*m+1] = fadd2(acc[2*m+1], (u64t)v.y);
        }
    }

    // ---- Phase B: local suffix + relu-dot ----
    float av = __ldg(&cosX[pid_sh[TC-1]*PP + pc]);
#pragma unroll 1
    for (int tt = TC - 1; tt >= 0; --tt) {
        float avn = (tt > 0) ? __ldg(&cosX[pid_sh[tt-1]*PP + pc]) : 0.f;
        u64t av2 = f2pk(av, av);
        const longlong2* g2 = (const longlong2*)&g_sh[tt*NKP + half*28];
#pragma unroll
        for (int m = 0; m < 7; ++m) {
            longlong2 gv = g2[m];
            acc[2*m]   = ffma2(av2, (u64t)gv.x, acc[2*m]);
            acc[2*m+1] = ffma2(av2, (u64t)gv.y, acc[2*m+1]);
        }
        float d0 = 0.f, d1 = 0.f, d2 = 0.f, d3 = 0.f;
#pragma unroll
        for (int m = 0; m < 7; ++m) {
            float2 a0 = f2up(acc[2*m]);
            float2 a1 = f2up(acc[2*m+1]);
            d0 = fmaf(fmaxf(a0.x, 0.f), w2r[4*m],   d0);
            d1 = fmaf(fmaxf(a0.y, 0.f), w2r[4*m+1], d1);
            d2 = fmaf(fmaxf(a1.x, 0.f), w2r[4*m+2], d2);
            d3 = fmaf(fmaxf(a1.y, 0.f), w2r[4*m+3], d3);
        }
        float d = (d0 + d1) + (d2 + d3);
        d += __shfl_xor_sync(0xffffffffu, d, 1);
        if (half == 0 && valid) out[(b*TT + t0 + tt)*PP + p] = d + b2v;
        av = avn;
    }

    // ---- counter reset for next graph replay ----
    if (tid == 0) {
        int old = atomicAdd(&q_done[qidx], 1);
        if (old == NC - 1) {
            atomicExch(&q_arrive[qidx], 0);
            atomicExch(&q_done[qidx], 0);
        }
    }
}

// ---------------------------------------------------------------------------
extern "C" void kernel_launch(void* const* d_in, const int* in_sizes, int n_in,
                              void* d_out, int out_size) {
    const int *pro_id = 0, *label = 0;
    const float *X = 0, *cos_X = 0, *onehot = 0, *Kmat = 0, *rec = 0,
                *bias = 0, *W1 = 0, *b1 = 0, *W2 = 0, *b2 = 0;

    int n_ones = 0;
    for (int i = 0; i < n_in; ++i) if (in_sizes[i] == 1) n_ones++;
    int ones_seen = 0;

    for (int i = 0; i < n_in; ++i) {
        switch (in_sizes[i]) {
            case 800:     if (!pro_id) pro_id = (const int*)d_in[i];
                          else         label  = (const int*)d_in[i];      break;
            case 128000:  X      = (const float*)d_in[i];                 break;
            case 1000000: cos_X  = (const float*)d_in[i];                 break;
            case 10000:   /* trimatrix: tril(ones) hardcoded */           break;
            case 512:     onehot = (const float*)d_in[i];                 break;
            case 65536:   Kmat   = (const float*)d_in[i];                 break;
            case 16384:   rec    = (const float*)d_in[i];                 break;
            case 256:     bias   = (const float*)d_in[i];                 break;
            case 9600:    W1     = (const float*)d_in[i];                 break;
            case 50:      if (!b1) b1 = (const float*)d_in[i];
                          else     W2 = (const float*)d_in[i];            break;
            case 1:       ones_seen++;
                          if (ones_seen == n_ones) b2 = (const float*)d_in[i];
                          break;
            default: break;
        }
    }

    float* out = (float*)d_out;

    k_pre <<<104*KQ + 125, 256>>>(pro_id, label, X, onehot, Kmat, W1, b1);
    k_lstm<<<BB, 256>>>(rec, bias, W1);
    k_main<<<dim3(8, BB, NC), 256>>>(pro_id, cos_X, W2, b2, out);
}

// round 14
// speedup vs baseline: 1.0808x; 1.0808x over previous
#include <cuda_runtime.h>

typedef unsigned long long u64t;

#define BB 8
#define TT 100
#define UU 64
#define ZZ 256   // 4U
#define PP 1000
#define NK 50
#define NKP 56   // padded row: [0..24]=k0..24, [25..27]=0, [28..52]=k25..49, [53..55]=0
#define BT (BB*TT) // 800
#define TC 20    // t-chunk size
#define NC 5     // number of chunks
#define KQ 4     // GEMM K-split factor (R9-proven)

// Scratch (__device__ globals — no allocation)
__device__ __align__(16) float d_xkq[KQ*BT*ZZ];  // xt @ kernel, K-quarters (no bias)
__device__ __align__(16) float d_g[BB*TT*NKP];   // ht @ W1[0:64], padded
__device__ __align__(16) float d_XW[1024*NKP];   // X @ W1[64:192] + b1, padded
__device__ __align__(16) float d_A[NC*BB*16*256*14];  // chunk totals (~9.2MB)

// ---- packed f32x2 helpers ---------------------------------------------------
__device__ __forceinline__ u64t f2pk(float lo, float hi) {
    u64t r; asm("mov.b64 %0,{%1,%2};" : "=l"(r) : "f"(lo), "f"(hi)); return r;
}
__device__ __forceinline__ u64t ffma2(u64t a, u64t b, u64t c) {
    u64t d; asm("fma.rn.f32x2 %0,%1,%2,%3;" : "=l"(d) : "l"(a), "l"(b), "l"(c)); return d;
}
__device__ __forceinline__ u64t fadd2(u64t a, u64t b) {
    u64t d; asm("add.rn.f32x2 %0,%1,%2;" : "=l"(d) : "l"(a), "l"(b)); return d;
}
__device__ __forceinline__ float2 f2up(u64t v) {
    float2 r; asm("mov.b64 {%0,%1},%2;" : "=f"(r.x), "=f"(r.y) : "l"(v)); return r;
}
__device__ __forceinline__ float tanha(float x) {
    float y; asm("tanh.approx.f32 %0, %1;" : "=f"(y) : "f"(x)); return y;
}
__device__ __forceinline__ float siga(float x) {
    return fmaf(0.5f, tanha(0.5f * x), 0.5f);
}
__device__ __forceinline__ int padpos(int k) { return (k < 25) ? k : k + 3; }

// ---------------------------------------------------------------------------
// k_pre: blocks 0..415   -> xk GEMM, K split in 4 quarters (64x32 tiles, K=64)
//        blocks 416..540 -> XW[p,:] = X[p,:] @ W1b + b1  (8 p per block)
// (R9-exact)
// ---------------------------------------------------------------------------
__global__ void __launch_bounds__(256) k_pre(
    const int* __restrict__ pro_id, const int* __restrict__ label,
    const float* __restrict__ X, const float* __restrict__ onehot,
    const float* __restrict__ Kmat,
    const float* __restrict__ W1, const float* __restrict__ b1) {
    __shared__ union {
        struct { float A[32][64]; float B[32][32]; } g;
        struct { float W[128*52]; float Xr[8][128]; } w;
    } sh;
    int tid = threadIdx.x;
    int bx = blockIdx.x;

    if (bx < 104*KQ) {
        int kquart = bx / 104;
        int sub    = bx % 104;
        int mblk = sub % 13, nblk = sub / 13;
        int rowBase = mblk * 64;
        int n0 = nblk * 32;
        int kbase = kquart * 64;
        float* xkout = d_xkq + kquart*BT*ZZ;
        int ty = tid >> 4, tx = tid & 15;

        int m0 = tid >> 3;
        int kq = (tid & 7) * 4;
        int row0 = rowBase + m0, row1 = rowBase + m0 + 32;
        bool v0 = row0 < BT, v1 = row1 < BT;
        const float *xp0 = 0, *op0 = 0, *xp1 = 0, *op1 = 0;
        if (v0) { xp0 = X + pro_id[row0]*128; op0 = onehot + label[row0]*ZZ; }
        if (v1) { xp1 = X + pro_id[row1]*128; op1 = onehot + label[row1]*ZZ; }

        u64t acc2[2][2] = {{0ull,0ull},{0ull,0ull}};

        for (int k0 = kbase; k0 < kbase + 64; k0 += 32) {
            int i0 = k0 + kq;
            {
                float4 v = make_float4(0.f,0.f,0.f,0.f);
                if (v0) {
                    float4 xv = *(const float4*)&xp0[i0 & 127];
                    float4 ov = *(const float4*)&op0[i0];
                    v = make_float4(xv.x*ov.x, xv.y*ov.y, xv.z*ov.z, xv.w*ov.w);
                }
                sh.g.A[kq+0][m0] = v.x; sh.g.A[kq+1][m0] = v.y;
                sh.g.A[kq+2][m0] = v.z; sh.g.A[kq+3][m0] = v.w;
            }
            {
                float4 v = make_float4(0.f,0.f,0.f,0.f);
                if (v1) {
                    float4 xv = *(const float4*)&xp1[i0 & 127];
                    float4 ov = *(const float4*)&op1[i0];
                    v = make_float4(xv.x*ov.x, xv.y*ov.y, xv.z*ov.z, xv.w*ov.w);
                }
                sh.g.A[kq+0][m0+32] = v.x; sh.g.A[kq+1][m0+32] = v.y;
                sh.g.A[kq+2][m0+32] = v.z; sh.g.A[kq+3][m0+32] = v.w;
            }
            {
                int kk = tid >> 3;
                int n4 = (tid & 7) * 4;
                *(float4*)&sh.g.B[kk][n4] = *(const float4*)&Kmat[(k0 + kk)*256 + n0 + n4];
            }
            __syncthreads();
#pragma unroll
            for (int kk = 0; kk < 32; ++kk) {
                longlong2 av = *(const longlong2*)&sh.g.A[kk][ty*4];
                float2 bv = *(const float2*)&sh.g.B[kk][tx*2];
                u64t bx0 = f2pk(bv.x, bv.x);
                u64t bx1 = f2pk(bv.y, bv.y);
                acc2[0][0] = ffma2((u64t)av.x, bx0, acc2[0][0]);
                acc2[1][0] = ffma2((u64t)av.y, bx0, acc2[1][0]);
                acc2[0][1] = ffma2((u64t)av.x, bx1, acc2[0][1]);
                acc2[1][1] = ffma2((u64t)av.y, bx1, acc2[1][1]);
            }
            __syncthreads();
        }
#pragma unroll
        for (int mp = 0; mp < 2; ++mp) {
            float2 c0 = f2up(acc2[mp][0]);
            float2 c1 = f2up(acc2[mp][1]);
            int r0 = rowBase + ty*4 + 2*mp;
            if (r0 < BT) {
                xkout[r0*ZZ + n0 + tx*2]     = c0.x;
                xkout[r0*ZZ + n0 + tx*2 + 1] = c1.x;
            }
            if (r0 + 1 < BT) {
                xkout[(r0+1)*ZZ + n0 + tx*2]     = c0.y;
                xkout[(r0+1)*ZZ + n0 + tx*2 + 1] = c1.y;
            }
        }
    } else {
        // ---- XW part ----
        int pbase = (bx - 104*KQ) * 8;
        for (int idx = tid; idx < 128*NK; idx += 256) {
            int j = idx / NK, k = idx - j*NK;
            sh.w.W[j*52 + k] = __ldg(&W1[(64 + j)*NK + k]);
        }
        {
            int pl = tid >> 5, quad = tid & 31;
            ((float4*)sh.w.Xr[pl])[quad] = *(const float4*)&X[(pbase + pl)*128 + quad*4];
        }
        __syncthreads();

        int pl = tid >> 5, lane = tid & 31;
        int p = pbase + pl;
        if (lane < 25) {
            int k2 = lane * 2;
            u64t acc = f2pk(__ldg(&b1[k2]), __ldg(&b1[k2+1]));
            const float* xr = sh.w.Xr[pl];
#pragma unroll 8
            for (int j = 0; j < 128; ++j) {
                float x = xr[j];
                acc = ffma2(f2pk(x, x), *(const u64t*)&sh.w.W[j*52 + k2], acc);
            }
            float2 r = f2up(acc);
            d_XW[p*NKP + padpos(k2)]     = r.x;
            d_XW[p*NKP + padpos(k2 + 1)] = r.y;
        } else if (lane < 31) {
            int off = (lane <= 27) ? lane : lane + 25;
            d_XW[p*NKP + off] = 0.f;
        }
    }
}

// ---------------------------------------------------------------------------
// k_lstm: R9-EXACT (the only validated-fast recurrence). Thread j owns rec
// column j (f32x2); activations by all 256 (grp), gates by warps 0-1;
// two __syncthreads per step. Epilogue computes g = ht @ W1a.
// ---------------------------------------------------------------------------
__global__ void __launch_bounds__(256) k_lstm(const float* __restrict__ rec,
                                              const float* __restrict__ bias,
                                              const float* __restrict__ W1) {
    int b = blockIdx.x;
    int j = threadIdx.x;
    __shared__ __align__(16) float h_hist[TT][UU];
    __shared__ float a_sh[ZZ];

    u64t rc2[32];
#pragma unroll
    for (int m = 0; m < 32; ++m)
        rc2[m] = f2pk(rec[(2*m)*ZZ + j], rec[(2*m+1)*ZZ + j]);

    float bs = __ldg(&bias[j]);
    int grp = j >> 6;
    float c = 0.f;

    const float* xq = d_xkq + b*TT*ZZ + j;
    float xs;
    {
        float s = bs;
#pragma unroll
        for (int q = 0; q < KQ; ++q) s += xq[q*BT*ZZ];
        xs = s;
    }

#pragma unroll 1
    for (int t = 0; t < TT; ++t) {
        float xk = xs;
        float nv[KQ];
#pragma unroll
        for (int q = 0; q < KQ; ++q) nv[q] = 0.f;
        if (t + 1 < TT) {
            int o = (t + 1) * ZZ;
#pragma unroll
            for (int q = 0; q < KQ; ++q) nv[q] = xq[o + q*BT*ZZ];
        }
        float z;
        if (t == 0) {
            z = xk;
        } else {
            const longlong2* h8 = (const longlong2*)h_hist[t-1];
            u64t z0 = f2pk(xk, 0.f), z1 = 0ull, z2 = 0ull, z3 = 0ull;
#pragma unroll
            for (int i = 0; i < 8; ++i) {
                longlong2 hA = h8[i], hB = h8[i+8];
                z0 = ffma2((u64t)hA.x, rc2[2*i],    z0);
                z1 = ffma2((u64t)hA.y, rc2[2*i+1],  z1);
                z2 = ffma2((u64t)hB.x, rc2[2*i+16], z2);
                z3 = ffma2((u64t)hB.y, rc2[2*i+17], z3);
            }
            float2 r = f2up(fadd2(fadd2(z0, z1), fadd2(z2, z3)));
            z = r.x + r.y;
        }
        a_sh[j] = (grp == 2) ? tanha(z) : siga(z);
        __syncthreads();
        if (j < UU) {
            float ai = a_sh[j], af = a_sh[64+j], ag = a_sh[128+j], ao = a_sh[192+j];
            c = fmaf(af, c, ai*ag);
            h_hist[t][j] = ao * tanha(c);
        }
        __syncthreads();
        {
            float s = bs;
#pragma unroll
            for (int q = 0; q < KQ; ++q) s += nv[q];
            xs = s;
        }
    }

    // epilogue: g[b,t,k] = sum_u h[t][u] * W1[u*50+k]
    int k = j & 63, tc = j >> 6;
    if (k < NK) {
        u64t w1c[32];
#pragma unroll
        for (int m = 0; m < 32; ++m)
            w1c[m] = f2pk(__ldg(&W1[(2*m)*NK + k]), __ldg(&W1[(2*m+1)*NK + k]));
        int off = padpos(k);
#pragma unroll 1
        for (int tt = tc*25; tt < tc*25 + 25; ++tt) {
            const longlong2* h8 = (const longlong2*)h_hist[tt];
            u64t g0 = 0ull, g1 = 0ull, g2 = 0ull, g3 = 0ull;
#pragma unroll
            for (int i = 0; i < 8; ++i) {
                longlong2 hA = h8[i], hB = h8[i+8];
                g0 = ffma2((u64t)hA.x, w1c[2*i],    g0);
                g1 = ffma2((u64t)hA.y, w1c[2*i+1],  g1);
                g2 = ffma2((u64t)hB.x, w1c[2*i+16], g2);
                g3 = ffma2((u64t)hB.y, w1c[2*i+17], g3);
            }
            float2 r = f2up(fadd2(fadd2(g0, g1), fadd2(g2, g3)));
            d_g[(b*TT + tt)*NKP + off] = r.x + r.y;
        }
    } else if (k < 56) {
        int off = (k >= 53) ? k : (k - 25);
        for (int tt = tc*25; tt < tc*25 + 25; ++tt)
            d_g[(b*TT + tt)*NKP + off] = 0.f;
    }
}

// ---------------------------------------------------------------------------
// 4-way k-split main, split into two kernels (launch boundary = barrier,
// deadlock-impossible at any grid size). 256 thr = 64 p x 4 k-quarters.
// Quarter q covers padded positions [q*14, q*14+14); pads are zero.
// ---------------------------------------------------------------------------
__global__ void __launch_bounds__(256) k_mainA(
    const int* __restrict__ pro_id, const float* __restrict__ cosX) {
    __shared__ __align__(16) float g_sh[TC*NKP];   // 17.9 KB
    __shared__ int pid_sh[TC];

    int pc16 = blockIdx.x;             // 0..15
    int b    = blockIdx.y;
    int c    = blockIdx.z + 1;         // chunks 1..NC-1
    int tid  = threadIdx.x;
    int t0   = c * TC;

    {
        const float4* gg = (const float4*)&d_g[(b*TT + t0)*NKP];
        float4* gs = (float4*)g_sh;
        for (int i = tid; i < (TC*NKP)/4; i += 256) gs[i] = gg[i];
        if (tid < TC) pid_sh[tid] = pro_id[b*TT + t0 + tid];
    }
    __syncthreads();

    int q  = tid & 3;
    int p  = pc16*64 + (tid >> 2);
    int pc = (p < PP) ? p : (PP - 1);

    u64t accA[7];
#pragma unroll
    for (int m = 0; m < 7; ++m) accA[m] = 0ull;

    float av = __ldg(&cosX[pid_sh[0]*PP + pc]);
#pragma unroll 1
    for (int tt = 0; tt < TC; ++tt) {
        float avn = (tt + 1 < TC) ? __ldg(&cosX[pid_sh[tt+1]*PP + pc]) : 0.f;
        u64t av2 = f2pk(av, av);
        const u64t* g2 = (const u64t*)&g_sh[tt*NKP + q*14];
#pragma unroll
        for (int m = 0; m < 7; ++m)
            accA[m] = ffma2(av2, g2[m], accA[m]);
        av = avn;
    }

    u64t* dst = (u64t*)&d_A[((long)((c*BB + b)*16 + pc16)*256 + tid) * 14];
#pragma unroll
    for (int m = 0; m < 7; ++m) dst[m] = accA[m];
}

__global__ void __launch_bounds__(256) k_mainB(
    const int* __restrict__ pro_id, const float* __restrict__ cosX,
    const float* __restrict__ W2, const float* __restrict__ b2,
    float* __restrict__ out) {
    __shared__ __align__(16) float g_sh[TC*NKP];
    __shared__ int pid_sh[TC];

    int pc16 = blockIdx.x;
    int b    = blockIdx.y;
    int c    = blockIdx.z;
    int tid  = threadIdx.x;
    int t0   = c * TC;

    {
        const float4* gg = (const float4*)&d_g[(b*TT + t0)*NKP];
        float4* gs = (float4*)g_sh;
        for (int i = tid; i < (TC*NKP)/4; i += 256) gs[i] = gg[i];
        if (tid < TC) pid_sh[tid] = pro_id[b*TT + t0 + tid];
    }
    __syncthreads();

    int q  = tid & 3;
    int p  = pc16*64 + (tid >> 2);
    bool valid = (p < PP);
    int pc = valid ? p : (PP - 1);

    u64t acc[7];
    float w2r[14];
    {
        const u64t* x2 = (const u64t*)&d_XW[p*NKP + q*14];
#pragma unroll
        for (int m = 0; m < 7; ++m) acc[m] = x2[m];
    }
#pragma unroll
    for (int jj = 0; jj < 14; ++jj) {
        int pos = q*14 + jj;
        int k = (pos < 25) ? pos : ((pos >= 28 && pos < 53) ? pos - 3 : -1);
        w2r[jj] = (k >= 0) ? __ldg(&W2[k]) : 0.f;
    }
    float b2v = __ldg(b2);

    // tail: sum A of chunks > c
    for (int c2 = c + 1; c2 < NC; ++c2) {
        const u64t* src = (const u64t*)&d_A[((long)((c2*BB + b)*16 + pc16)*256 + tid) * 14];
#pragma unroll
        for (int m = 0; m < 7; ++m) acc[m] = fadd2(acc[m], src[m]);
    }

    // local suffix + relu-dot
    float av = __ldg(&cosX[pid_sh[TC-1]*PP + pc]);
#pragma unroll 1
    for (int tt = TC - 1; tt >= 0; --tt) {
        float avn = (tt > 0) ? __ldg(&cosX[pid_sh[tt-1]*PP + pc]) : 0.f;
        u64t av2 = f2pk(av, av);
        const u64t* g2 = (const u64t*)&g_sh[tt*NKP + q*14];
#pragma unroll
        for (int m = 0; m < 7; ++m)
            acc[m] = ffma2(av2, g2[m], acc[m]);
        float d0 = 0.f, d1 = 0.f;
#pragma unroll
        for (int m = 0; m < 7; ++m) {
            float2 a0 = f2up(acc[m]);
            d0 = fmaf(fmaxf(a0.x, 0.f), w2r[2*m],   d0);
            d1 = fmaf(fmaxf(a0.y, 0.f), w2r[2*m+1], d1);
        }
        float d = d0 + d1;
        d += __shfl_xor_sync(0xffffffffu, d, 1);
        d += __shfl_xor_sync(0xffffffffu, d, 2);
        if (q == 0 && valid) out[(b*TT + t0 + tt)*PP + p] = d + b2v;
        av = avn;
    }
}

// ---------------------------------------------------------------------------
extern "C" void kernel_launch(void* const* d_in, const int* in_sizes, int n_in,
                              void* d_out, int out_size) {
    const int *pro_id = 0, *label = 0;
    const float *X = 0, *cos_X = 0, *onehot = 0, *Kmat = 0, *rec = 0,
                *bias = 0, *W1 = 0, *b1 = 0, *W2 = 0, *b2 = 0;

    int n_ones = 0;
    for (int i = 0; i < n_in; ++i) if (in_sizes[i] == 1) n_ones++;
    int ones_seen = 0;

    for (int i = 0; i < n_in; ++i) {
        switch (in_sizes[i]) {
            case 800:     if (!pro_id) pro_id = (const int*)d_in[i];
                          else         label  = (const int*)d_in[i];      break;
            case 128000:  X      = (const float*)d_in[i];                 break;
            case 1000000: cos_X  = (const float*)d_in[i];                 break;
            case 10000:   /* trimatrix: tril(ones) hardcoded */           break;
            case 512:     onehot = (const float*)d_in[i];                 break;
            case 65536:   Kmat   = (const float*)d_in[i];                 break;
            case 16384:   rec    = (const float*)d_in[i];                 break;
            case 256:     bias   = (const float*)d_in[i];                 break;
            case 9600:    W1     = (const float*)d_in[i];                 break;
            case 50:      if (!b1) b1 = (const float*)d_in[i];
                          else     W2 = (const float*)d_in[i];            break;
            case 1:       ones_seen++;
                          if (ones_seen == n_ones) b2 = (const float*)d_in[i];
                          break;
            default: break;
        }
    }

    float* out = (float*)d_out;

    k_pre  <<<104*KQ + 125, 256>>>(pro_id, label, X, onehot, Kmat, W1, b1);
    k_lstm <<<BB, 256>>>(rec, bias, W1);
    k_mainA<<<dim3(16, BB, NC-1), 256>>>(pro_id, cos_X);
    k_mainB<<<dim3(16, BB, NC),   256>>>(pro_id, cos_X, W2, b2, out);
}

// round 15
// speedup vs baseline: 1.4434x; 1.3355x over previous
#include <cuda_runtime.h>

typedef unsigned long long u64t;

#define BB 8
#define TT 100
#define UU 64
#define ZZ 256   // 4U
#define PP 1000
#define NK 50
#define NKP 56   // padded row: [0..24]=k0..24, [25..27]=0, [28..52]=k25..49, [53..55]=0
#define BT (BB*TT) // 800
#define TC 20    // t-chunk size
#define NC 5     // number of chunks
#define KQ 4     // GEMM K-split factor

// Scratch (__device__ globals — no allocation)
__device__ __align__(16) float d_xkq[KQ*BT*ZZ];  // xt @ kernel, 4 K-quarters (no bias)
__device__ __align__(16) float d_g[BB*TT*NKP];   // ht @ W1[0:64], padded
__device__ __align__(16) float d_XW[1024*NKP];   // X @ W1[64:192] + b1, padded
__device__ __align__(16) float d_A[NC*BB*8*256*28];  // chunk totals

// per-(b,pchunk) sync counters, self-resetting
__device__ int q_arrive[64];
__device__ int q_done[64];

// ---- packed f32x2 helpers ---------------------------------------------------
__device__ __forceinline__ u64t f2pk(float lo, float hi) {
    u64t r; asm("mov.b64 %0,{%1,%2};" : "=l"(r) : "f"(lo), "f"(hi)); return r;
}
__device__ __forceinline__ u64t ffma2(u64t a, u64t b, u64t c) {
    u64t d; asm("fma.rn.f32x2 %0,%1,%2,%3;" : "=l"(d) : "l"(a), "l"(b), "l"(c)); return d;
}
__device__ __forceinline__ u64t fadd2(u64t a, u64t b) {
    u64t d; asm("add.rn.f32x2 %0,%1,%2;" : "=l"(d) : "l"(a), "l"(b)); return d;
}
__device__ __forceinline__ float2 f2up(u64t v) {
    float2 r; asm("mov.b64 {%0,%1},%2;" : "=f"(r.x), "=f"(r.y) : "l"(v)); return r;
}
__device__ __forceinline__ float tanha(float x) {
    float y; asm("tanh.approx.f32 %0, %1;" : "=f"(y) : "f"(x)); return y;
}
__device__ __forceinline__ float siga(float x) {
    return fmaf(0.5f, tanha(0.5f * x), 0.5f);
}
__device__ __forceinline__ int padpos(int k) { return (k < 25) ? k : k + 3; }

__device__ __forceinline__ int ld_acq(int* p) {
    int v; asm volatile("ld.acquire.gpu.global.s32 %0, [%1];" : "=r"(v) : "l"(p) : "memory");
    return v;
}

// ---------------------------------------------------------------------------
// k_pre: blocks 0..415   -> xk GEMM, K split in 4 quarters (64x32 tiles, K=64)
//        blocks 416..540 -> XW[p,:] = X[p,:] @ W1b + b1  (8 p per block)
// ---------------------------------------------------------------------------
__global__ void __launch_bounds__(256) k_pre(
    const int* __restrict__ pro_id, const int* __restrict__ label,
    const float* __restrict__ X, const float* __restrict__ onehot,
    const float* __restrict__ Kmat,
    const float* __restrict__ W1, const float* __restrict__ b1) {
    __shared__ union {
        struct { float A[32][64]; float B[32][32]; } g;
        struct { float W[128*52]; float Xr[8][128]; } w;
    } sh;
    int tid = threadIdx.x;
    int bx = blockIdx.x;

    if (bx < 104*KQ) {
        int kquart = bx / 104;
        int sub    = bx % 104;
        int mblk = sub % 13, nblk = sub / 13;
        int rowBase = mblk * 64;
        int n0 = nblk * 32;
        int kbase = kquart * 64;
        float* xkout = d_xkq + kquart*BT*ZZ;
        int ty = tid >> 4, tx = tid & 15;

        int m0 = tid >> 3;
        int kq = (tid & 7) * 4;
        int row0 = rowBase + m0, row1 = rowBase + m0 + 32;
        bool v0 = row0 < BT, v1 = row1 < BT;
        const float *xp0 = 0, *op0 = 0, *xp1 = 0, *op1 = 0;
        if (v0) { xp0 = X + pro_id[row0]*128; op0 = onehot + label[row0]*ZZ; }
        if (v1) { xp1 = X + pro_id[row1]*128; op1 = onehot + label[row1]*ZZ; }

        u64t acc2[2][2] = {{0ull,0ull},{0ull,0ull}};

        for (int k0 = kbase; k0 < kbase + 64; k0 += 32) {
            int i0 = k0 + kq;
            {
                float4 v = make_float4(0.f,0.f,0.f,0.f);
                if (v0) {
                    float4 xv = *(const float4*)&xp0[i0 & 127];
                    float4 ov = *(const float4*)&op0[i0];
                    v = make_float4(xv.x*ov.x, xv.y*ov.y, xv.z*ov.z, xv.w*ov.w);
                }
                sh.g.A[kq+0][m0] = v.x; sh.g.A[kq+1][m0] = v.y;
                sh.g.A[kq+2][m0] = v.z; sh.g.A[kq+3][m0] = v.w;
            }
            {
                float4 v = make_float4(0.f,0.f,0.f,0.f);
                if (v1) {
                    float4 xv = *(const float4*)&xp1[i0 & 127];
                    float4 ov = *(const float4*)&op1[i0];
                    v = make_float4(xv.x*ov.x, xv.y*ov.y, xv.z*ov.z, xv.w*ov.w);
                }
                sh.g.A[kq+0][m0+32] = v.x; sh.g.A[kq+1][m0+32] = v.y;
                sh.g.A[kq+2][m0+32] = v.z; sh.g.A[kq+3][m0+32] = v.w;
            }
            {
                int kk = tid >> 3;
                int n4 = (tid & 7) * 4;
                *(float4*)&sh.g.B[kk][n4] = *(const float4*)&Kmat[(k0 + kk)*256 + n0 + n4];
            }
            __syncthreads();
#pragma unroll
            for (int kk = 0; kk < 32; ++kk) {
                longlong2 av = *(const longlong2*)&sh.g.A[kk][ty*4];
                float2 bv = *(const float2*)&sh.g.B[kk][tx*2];
                u64t bx0 = f2pk(bv.x, bv.x);
                u64t bx1 = f2pk(bv.y, bv.y);
                acc2[0][0] = ffma2((u64t)av.x, bx0, acc2[0][0]);
                acc2[1][0] = ffma2((u64t)av.y, bx0, acc2[1][0]);
                acc2[0][1] = ffma2((u64t)av.x, bx1, acc2[0][1]);
                acc2[1][1] = ffma2((u64t)av.y, bx1, acc2[1][1]);
            }
            __syncthreads();
        }
#pragma unroll
        for (int mp = 0; mp < 2; ++mp) {
            float2 c0 = f2up(acc2[mp][0]);
            float2 c1 = f2up(acc2[mp][1]);
            int r0 = rowBase + ty*4 + 2*mp;
            if (r0 < BT) {
                xkout[r0*ZZ + n0 + tx*2]     = c0.x;
                xkout[r0*ZZ + n0 + tx*2 + 1] = c1.x;
            }
            if (r0 + 1 < BT) {
                xkout[(r0+1)*ZZ + n0 + tx*2]     = c0.y;
                xkout[(r0+1)*ZZ + n0 + tx*2 + 1] = c1.y;
            }
        }
    } else {
        // ---- XW part ----
        int pbase = (bx - 104*KQ) * 8;
        for (int idx = tid; idx < 128*NK; idx += 256) {
            int j = idx / NK, k = idx - j*NK;
            sh.w.W[j*52 + k] = __ldg(&W1[(64 + j)*NK + k]);
        }
        {
            int pl = tid >> 5, quad = tid & 31;
            ((float4*)sh.w.Xr[pl])[quad] = *(const float4*)&X[(pbase + pl)*128 + quad*4];
        }
        __syncthreads();

        int pl = tid >> 5, lane = tid & 31;
        int p = pbase + pl;
        if (lane < 25) {
            int k2 = lane * 2;
            u64t acc = f2pk(__ldg(&b1[k2]), __ldg(&b1[k2+1]));
            const float* xr = sh.w.Xr[pl];
#pragma unroll 8
            for (int j = 0; j < 128; ++j) {
                float x = xr[j];
                acc = ffma2(f2pk(x, x), *(const u64t*)&sh.w.W[j*52 + k2], acc);
            }
            float2 r = f2up(acc);
            d_XW[p*NKP + padpos(k2)]     = r.x;
            d_XW[p*NKP + padpos(k2 + 1)] = r.y;
        } else if (lane < 31) {
            int off = (lane <= 27) ? lane : lane + 25;
            d_XW[p*NKP + off] = 0.f;
        }
    }
}

// ---------------------------------------------------------------------------
// k_lstm: one block per batch; thread j owns rec column j (f32x2 packed).
// xk = sum of 4 K-quarter partials + bias (prefetched). tanh.approx gates.
// ---------------------------------------------------------------------------
__global__ void __launch_bounds__(256) k_lstm(const float* __restrict__ rec,
                                              const float* __restrict__ bias,
                                              const float* __restrict__ W1) {
    int b = blockIdx.x;
    int j = threadIdx.x;
    __shared__ __align__(16) float h_hist[TT][UU];
    __shared__ float a_sh[ZZ];

    u64t rc2[32];
#pragma unroll
    for (int m = 0; m < 32; ++m)
        rc2[m] = f2pk(rec[(2*m)*ZZ + j], rec[(2*m+1)*ZZ + j]);

    float bs = __ldg(&bias[j]);
    int grp = j >> 6;
    float c = 0.f;

    const float* xq = d_xkq + b*TT*ZZ + j;
    float xs;
    {
        float a0 = xq[0];
        float a1 = xq[BT*ZZ];
        float a2 = xq[2*BT*ZZ];
        float a3 = xq[3*BT*ZZ];
        xs = ((a0 + a1) + (a2 + a3)) + bs;
    }

#pragma unroll 1
    for (int t = 0; t < TT; ++t) {
        float xk = xs;
        float n0v = 0.f, n1v = 0.f, n2v = 0.f, n3v = 0.f;
        if (t + 1 < TT) {
            int o = (t + 1) * ZZ;
            n0v = xq[o];
            n1v = xq[o + BT*ZZ];
            n2v = xq[o + 2*BT*ZZ];
            n3v = xq[o + 3*BT*ZZ];
        }
        float z;
        if (t == 0) {
            z = xk;
        } else {
            const longlong2* h8 = (const longlong2*)h_hist[t-1];
            u64t z0 = f2pk(xk, 0.f), z1 = 0ull, z2 = 0ull, z3 = 0ull;
#pragma unroll
            for (int i = 0; i < 8; ++i) {
                longlong2 hA = h8[i], hB = h8[i+8];
                z0 = ffma2((u64t)hA.x, rc2[2*i],    z0);
                z1 = ffma2((u64t)hA.y, rc2[2*i+1],  z1);
                z2 = ffma2((u64t)hB.x, rc2[2*i+16], z2);
                z3 = ffma2((u64t)hB.y, rc2[2*i+17], z3);
            }
            float2 r = f2up(fadd2(fadd2(z0, z1), fadd2(z2, z3)));
            z = r.x + r.y;
        }
        a_sh[j] = (grp == 2) ? tanha(z) : siga(z);
        __syncthreads();
        if (j < UU) {
            float ai = a_sh[j], af = a_sh[64+j], ag = a_sh[128+j], ao = a_sh[192+j];
            c = fmaf(af, c, ai*ag);
            h_hist[t][j] = ao * tanha(c);
        }
        __syncthreads();
        xs = ((n0v + n1v) + (n2v + n3v)) + bs;
    }

    // epilogue: g[b,t,k] = sum_u h[t][u] * W1[u*50+k]
    int k = j & 63, tc = j >> 6;
    if (k < NK) {
        u64t w1c[32];
#pragma unroll
        for (int m = 0; m < 32; ++m)
            w1c[m] = f2pk(__ldg(&W1[(2*m)*NK + k]), __ldg(&W1[(2*m+1)*NK + k]));
        int off = padpos(k);
#pragma unroll 1
        for (int tt = tc*25; tt < tc*25 + 25; ++tt) {
            const longlong2* h8 = (const longlong2*)h_hist[tt];
            u64t g0 = 0ull, g1 = 0ull, g2 = 0ull, g3 = 0ull;
#pragma unroll
            for (int i = 0; i < 8; ++i) {
                longlong2 hA = h8[i], hB = h8[i+8];
                g0 = ffma2((u64t)hA.x, w1c[2*i],    g0);
                g1 = ffma2((u64t)hA.y, w1c[2*i+1],  g1);
                g2 = ffma2((u64t)hB.x, w1c[2*i+16], g2);
                g3 = ffma2((u64t)hB.y, w1c[2*i+17], g3);
            }
            float2 r = f2up(fadd2(fadd2(g0, g1), fadd2(g2, g3)));
            d_g[(b*TT + tt)*NKP + off] = r.x + r.y;
        }
    } else if (k < 56) {
        int off = (k >= 53) ? k : (k - 25);
        for (int tt = tc*25; tt < tc*25 + 25; ++tt)
            d_g[(b*TT + tt)*NKP + off] = 0.f;
    }
}

// ---------------------------------------------------------------------------
// k_main: two-level suffix scan, packed f32x2. Grid (pchunk=8, b=8, c=5)
// = 320 blocks, safely co-resident for the quartet spin-sync.
// ---------------------------------------------------------------------------
__global__ void __launch_bounds__(256) k_main(
    const int* __restrict__ pro_id, const float* __restrict__ cosX,
    const float* __restrict__ W2, const float* __restrict__ b2,
    float* __restrict__ out) {
    __shared__ __align__(16) float g_sh[TC*NKP];
    __shared__ int pid_sh[TC];

    int pc8 = blockIdx.x;
    int b   = blockIdx.y;
    int c   = blockIdx.z;
    int tid = threadIdx.x;
    int t0  = c * TC;
    int qidx = b*8 + pc8;

    {
        const float4* gg = (const float4*)&d_g[(b*TT + t0)*NKP];
        float4* gs = (float4*)g_sh;
        for (int i = tid; i < (TC*NKP)/4; i += 256) gs[i] = gg[i];
        if (tid < TC) pid_sh[tid] = pro_id[b*TT + t0 + tid];
    }
    __syncthreads();

    int p    = pc8*128 + (tid >> 1);
    int half = tid & 1;
    bool valid = (p < PP);
    int pc = valid ? p : (PP - 1);

    long aoff = ((long)((c*BB + b)*8 + pc8)*256 + tid) * 28;

    // ---- Phase A: own-chunk total (c>0 only), packed ----
    if (c > 0) {
        u64t accA[14];
#pragma unroll
        for (int m = 0; m < 14; ++m) accA[m] = 0ull;
#pragma unroll 1
        for (int tt = 0; tt < TC; ++tt) {
            float av = __ldg(&cosX[pid_sh[tt]*PP + pc]);
            u64t av2 = f2pk(av, av);
            const longlong2* g2 = (const longlong2*)&g_sh[tt*NKP + half*28];
#pragma unroll
            for (int m = 0; m < 7; ++m) {
                longlong2 gv = g2[m];
                accA[2*m]   = ffma2(av2, (u64t)gv.x, accA[2*m]);
                accA[2*m+1] = ffma2(av2, (u64t)gv.y, accA[2*m+1]);
            }
        }
        longlong2* dst = (longlong2*)&d_A[aoff];
#pragma unroll
        for (int m = 0; m < 7; ++m)
            dst[m] = make_longlong2((long long)accA[2*m], (long long)accA[2*m+1]);
        __threadfence();
    }
    __syncthreads();
    if (tid == 0)
        asm volatile("red.release.gpu.global.add.s32 [%0], 1;" :: "l"(&q_arrive[qidx]) : "memory");

    // ---- preload while waiting ----
    u64t acc[14];
    float w2r[28];
    {
        const longlong2* x2 = (const longlong2*)&d_XW[p*NKP + half*28];
#pragma unroll
        for (int m = 0; m < 7; ++m) {
            longlong2 v = x2[m];
            acc[2*m] = (u64t)v.x; acc[2*m+1] = (u64t)v.y;
        }
    }
#pragma unroll
    for (int jj = 0; jj < 28; ++jj)
        w2r[jj] = (jj < 25) ? __ldg(&W2[half*25 + jj]) : 0.f;
    float b2v = __ldg(b2);

    // ---- wait for all chunks of this (b,pchunk) ----
    if (tid == 0) {
        while (ld_acq(&q_arrive[qidx]) < NC) __nanosleep(60);
    }
    __syncthreads();

    // ---- tail: sum A of chunks > c ----
    for (int c2 = c + 1; c2 < NC; ++c2) {
        long o2 = ((long)((c2*BB + b)*8 + pc8)*256 + tid) * 28;
        const longlong2* src = (const longlong2*)&d_A[o2];
#pragma unroll
        for (int m = 0; m < 7; ++m) {
            longlong2 v = src[m];
            acc[2*m]   = fadd2(acc[2*m],   (u64t)v.x);
            acc[2*m+1] = fadd2(acc[2*m+1], (u64t)v.y);
        }
    }

    // ---- Phase B: local suffix + relu-dot ----
#pragma unroll 1
    for (int tt = TC - 1; tt >= 0; --tt) {
        float av = __ldg(&cosX[pid_sh[tt]*PP + pc]);
        u64t av2 = f2pk(av, av);
        const longlong2* g2 = (const longlong2*)&g_sh[tt*NKP + half*28];
#pragma unroll
        for (int m = 0; m < 7; ++m) {
            longlong2 gv = g2[m];
            acc[2*m]   = ffma2(av2, (u64t)gv.x, acc[2*m]);
            acc[2*m+1] = ffma2(av2, (u64t)gv.y, acc[2*m+1]);
        }
        float d0 = 0.f, d1 = 0.f, d2 = 0.f, d3 = 0.f;
#pragma unroll
        for (int m = 0; m < 7; ++m) {
            float2 a0 = f2up(acc[2*m]);
            float2 a1 = f2up(acc[2*m+1]);
            d0 = fmaf(fmaxf(a0.x, 0.f), w2r[4*m],   d0);
            d1 = fmaf(fmaxf(a0.y, 0.f), w2r[4*m+1], d1);
            d2 = fmaf(fmaxf(a1.x, 0.f), w2r[4*m+2], d2);
            d3 = fmaf(fmaxf(a1.y, 0.f), w2r[4*m+3], d3);
        }
        float d = (d0 + d1) + (d2 + d3);
        d += __shfl_xor_sync(0xffffffffu, d, 1);
        if (half == 0 && valid) out[(b*TT + t0 + tt)*PP + p] = d + b2v;
    }

    // ---- counter reset for next graph replay ----
    if (tid == 0) {
        int old = atomicAdd(&q_done[qidx], 1);
        if (old == NC - 1) {
            atomicExch(&q_arrive[qidx], 0);
            atomicExch(&q_done[qidx], 0);
        }
    }
}

// ---------------------------------------------------------------------------
extern "C" void kernel_launch(void* const* d_in, const int* in_sizes, int n_in,
                              void* d_out, int out_size) {
    const int *pro_id = 0, *label = 0;
    const float *X = 0, *cos_X = 0, *onehot = 0, *Kmat = 0, *rec = 0,
                *bias = 0, *W1 = 0, *b1 = 0, *W2 = 0, *b2 = 0;

    int n_ones = 0;
    for (int i = 0; i < n_in; ++i) if (in_sizes[i] == 1) n_ones++;
    int ones_seen = 0;

    for (int i = 0; i < n_in; ++i) {
        switch (in_sizes[i]) {
            case 800:     if (!pro_id) pro_id = (const int*)d_in[i];
                          else         label  = (const int*)d_in[i];      break;
            case 128000:  X      = (const float*)d_in[i];                 break;
            case 1000000: cos_X  = (const float*)d_in[i];                 break;
            case 10000:   /* trimatrix: tril(ones) hardcoded */           break;
            case 512:     onehot = (const float*)d_in[i];                 break;
            case 65536:   Kmat   = (const float*)d_in[i];                 break;
            case 16384:   rec    = (const float*)d_in[i];                 break;
            case 256:     bias   = (const float*)d_in[i];                 break;
            case 9600:    W1     = (const float*)d_in[i];                 break;
            case 50:      if (!b1) b1 = (const float*)d_in[i];
                          else     W2 = (const float*)d_in[i];            break;
            case 1:       ones_seen++;
                          if (ones_seen == n_ones) b2 = (const float*)d_in[i];
                          break;
            default: break;
        }
    }

    float* out = (float*)d_out;

    k_pre <<<104*KQ + 125, 256>>>(pro_id, label, X, onehot, Kmat, W1, b1);
    k_lstm<<<BB, 256>>>(rec, bias, W1);
    k_main<<<dim3(8, BB, NC), 256>>>(pro_id, cos_X, W2, b2, out);
}